// round 1
// baseline (speedup 1.0000x reference)
#include <cuda_runtime.h>
#include <math.h>

// ---------------------------------------------------------------------------
// Differentiable JPEG (quality 80) forward pass, fused single kernel.
// image [B,3,512,512] fp32 -> out same shape.
// Tile = 16x16 pixels = 4 Y blocks + 1 Cb + 1 Cr (chroma 2x2-downsampled).
// One CTA (64 threads) per tile; each thread owns a 2x2 pixel quad.
// ---------------------------------------------------------------------------

#define IMG_H 512
#define IMG_W 512

__device__ float g_C[64];      // C[x][u] = cos((2x+1)u*pi/16)
__device__ float g_A[2][64];   // (ALPHA*0.25)/q  : DCT-scale / quant step
__device__ float g_B[2][64];   // (ALPHA*0.25)*q  : dequant * IDCT-scale

__constant__ float c_YTAB[64] = {
    16,11,10,16,24,40,51,61,  12,12,14,19,26,58,60,55,
    14,13,16,24,40,57,69,56,  14,17,22,29,51,87,80,62,
    18,22,37,56,68,109,103,77, 24,35,55,64,81,104,113,92,
    49,64,78,87,103,121,120,101, 72,92,95,98,112,100,103,99};
__constant__ float c_CTAB[64] = {
    17,18,24,47,99,99,99,99,  18,21,26,66,99,99,99,99,
    24,26,56,99,99,99,99,99,  47,66,99,99,99,99,99,99,
    99,99,99,99,99,99,99,99,  99,99,99,99,99,99,99,99,
    99,99,99,99,99,99,99,99,  99,99,99,99,99,99,99,99};

// QUALITY = 80 -> FACTOR = (200 - 160)/100 = 0.4
#define QFACTOR 0.4

__global__ void init_tables_kernel() {
    int t = threadIdx.x;               // 0..63
    int x = t >> 3, u = t & 7;
    double cv = cos((2.0 * x + 1.0) * u * 3.14159265358979323846 / 16.0);
    g_C[t] = (float)cv;

    // quant-scale tables indexed [u][v] = [x][u] reuse of t
    double au = (x == 0) ? 0.70710678118654752440 : 1.0;
    double av = (u == 0) ? 0.70710678118654752440 : 1.0;
    float S  = (float)(au * av * 0.25);
    float qy = (float)((double)c_YTAB[t] * QFACTOR);
    float qc = (float)((double)c_CTAB[t] * QFACTOR);
    g_A[0][t] = S / qy;  g_B[0][t] = S * qy;
    g_A[1][t] = S / qc;  g_B[1][t] = S * qc;
}

__global__ void __launch_bounds__(64)
jpeg_tile_kernel(const float* __restrict__ img, float* __restrict__ out) {
    __shared__ float sC[64];
    __shared__ float sA[2][64];
    __shared__ float sB[2][64];
    __shared__ float s1[6][8][9];   // blocks 0..3 = Y, 4 = Cb, 5 = Cr
    __shared__ float s2[6][8][9];

    const int t = threadIdx.x;
    sC[t]    = g_C[t];
    sA[0][t] = g_A[0][t];  sA[1][t] = g_A[1][t];
    sB[0][t] = g_B[0][t];  sB[1][t] = g_B[1][t];

    const int tile = blockIdx.x;
    const int tx   = tile & 31;
    const int ty   = (tile >> 5) & 31;
    const int bimg = tile >> 10;

    const int qx = t & 7, qy = t >> 3;        // quad coords in tile (8x8 quads)
    const int px = tx * 16 + qx * 2;          // top-left pixel of quad
    const int py = ty * 16 + qy * 2;

    const size_t plane = (size_t)IMG_H * IMG_W;
    const float* pR = img + (size_t)bimg * 3 * plane + (size_t)py * IMG_W + px;
    const float* pG = pR + plane;
    const float* pB = pR + 2 * plane;

    float2 r0 = *(const float2*)pR;
    float2 r1 = *(const float2*)(pR + IMG_W);
    float2 g0 = *(const float2*)pG;
    float2 g1 = *(const float2*)(pG + IMG_W);
    float2 b0 = *(const float2*)pB;
    float2 b1 = *(const float2*)(pB + IMG_W);

    float Rq[2][2] = {{r0.x, r0.y}, {r1.x, r1.y}};
    float Gq[2][2] = {{g0.x, g0.y}, {g1.x, g1.y}};
    float Bq[2][2] = {{b0.x, b0.y}, {b1.x, b1.y}};

    float cbs = 0.f, crs = 0.f;
    #pragma unroll
    for (int dr = 0; dr < 2; dr++) {
        #pragma unroll
        for (int dc = 0; dc < 2; dc++) {
            float r = Rq[dr][dc] * 255.f;
            float g = Gq[dr][dc] * 255.f;
            float b = Bq[dr][dc] * 255.f;
            // Y shifted by -128 (folded DCT level shift)
            float y = 0.299f * r + 0.587f * g + 0.114f * b - 128.f;
            // Cb/Cr: +128 shift and DCT -128 cancel -> raw matrix part
            cbs += -0.168736f * r - 0.331264f * g + 0.5f      * b;
            crs +=  0.5f      * r - 0.418688f * g - 0.081312f * b;
            int prow = qy * 2 + dr, pcol = qx * 2 + dc;
            int blk = ((prow >> 3) << 1) + (pcol >> 3);
            s1[blk][prow & 7][pcol & 7] = y;
        }
    }
    s1[4][qy][qx] = cbs * 0.25f;
    s1[5][qy][qx] = crs * 0.25f;
    __syncthreads();

    // ---- Stage A: 1-D DCT along rows-dim (x): s2[b][u][j] = sum_x C[x][u]*s1[b][x][j]
    if (t < 48) {
        int blk = t >> 3, j = t & 7;
        float in[8];
        #pragma unroll
        for (int x = 0; x < 8; x++) in[x] = s1[blk][x][j];
        #pragma unroll
        for (int u = 0; u < 8; u++) {
            float acc = 0.f;
            #pragma unroll
            for (int x = 0; x < 8; x++) acc += in[x] * sC[x * 8 + u];
            s2[blk][u][j] = acc;
        }
    }
    __syncthreads();

    // ---- Stage B: DCT along cols-dim, quantize w/ diff_round, start IDCT (v-sum)
    if (t < 48) {
        int blk = t >> 3, u = t & 7;
        int ti = (blk < 4) ? 0 : 1;
        float row[8];
        #pragma unroll
        for (int y = 0; y < 8; y++) row[y] = s2[blk][u][y];
        float h[8];
        #pragma unroll
        for (int v = 0; v < 8; v++) {
            float raw = 0.f;
            #pragma unroll
            for (int y = 0; y < 8; y++) raw += row[y] * sC[y * 8 + v];
            float c = raw * sA[ti][u * 8 + v];   // coef / q
            float r = rintf(c);                  // round-half-even == jnp.round
            float d = c - r;
            h[v] = (r + d * d * d) * sB[ti][u * 8 + v];  // * q * (ALPHA*0.25)
        }
        #pragma unroll
        for (int y = 0; y < 8; y++) {
            float acc = 0.f;
            #pragma unroll
            for (int v = 0; v < 8; v++) acc += h[v] * sC[y * 8 + v];
            s1[blk][u][y] = acc;
        }
    }
    __syncthreads();

    // ---- Stage C: finish IDCT (u-sum): s2[b][x][j] = sum_u C[x][u]*s1[b][u][j]
    if (t < 48) {
        int blk = t >> 3, j = t & 7;
        float in[8];
        #pragma unroll
        for (int u = 0; u < 8; u++) in[u] = s1[blk][u][j];
        float add = (blk < 4) ? 128.f : 0.f;   // chroma +128/-128 cancels
        #pragma unroll
        for (int x = 0; x < 8; x++) {
            float acc = 0.f;
            #pragma unroll
            for (int u = 0; u < 8; u++) acc += in[u] * sC[x * 8 + u];
            s2[blk][x][j] = acc + add;
        }
    }
    __syncthreads();

    // ---- Writeback: upsample chroma (same value across quad), YCbCr->RGB, clip
    float cb = s2[4][qy][qx];
    float cr = s2[5][qy][qx];

    float* qR = out + (size_t)bimg * 3 * plane + (size_t)py * IMG_W + px;
    float* qG = qR + plane;
    float* qB = qR + 2 * plane;

    #pragma unroll
    for (int dr = 0; dr < 2; dr++) {
        float2 ro, go, bo;
        float* pr_out[2] = {&ro.x, &ro.y};
        float* pg_out[2] = {&go.x, &go.y};
        float* pb_out[2] = {&bo.x, &bo.y};
        #pragma unroll
        for (int dc = 0; dc < 2; dc++) {
            int prow = qy * 2 + dr, pcol = qx * 2 + dc;
            int blk = ((prow >> 3) << 1) + (pcol >> 3);
            float y = s2[blk][prow & 7][pcol & 7];
            float Rv = y + 1.402f * cr;
            float Gv = y - 0.344136f * cb - 0.714136f * cr;
            float Bv = y + 1.772f * cb;
            Rv = fminf(fmaxf(Rv, 0.f), 255.f) * (1.f / 255.f);
            Gv = fminf(fmaxf(Gv, 0.f), 255.f) * (1.f / 255.f);
            Bv = fminf(fmaxf(Bv, 0.f), 255.f) * (1.f / 255.f);
            *pr_out[dc] = Rv; *pg_out[dc] = Gv; *pb_out[dc] = Bv;
        }
        *(float2*)(qR + dr * IMG_W) = ro;
        *(float2*)(qG + dr * IMG_W) = go;
        *(float2*)(qB + dr * IMG_W) = bo;
    }
}

extern "C" void kernel_launch(void* const* d_in, const int* in_sizes, int n_in,
                              void* d_out, int out_size) {
    const float* img = (const float*)d_in[0];
    float* out = (float*)d_out;
    int batch = in_sizes[0] / (3 * IMG_H * IMG_W);   // 32
    int tiles = batch * (IMG_H / 16) * (IMG_W / 16); // 32768

    init_tables_kernel<<<1, 64>>>();
    jpeg_tile_kernel<<<tiles, 64>>>(img, out);
}

// round 2
// speedup vs baseline: 1.4643x; 1.4643x over previous
#include <cuda_runtime.h>
#include <math.h>

// ---------------------------------------------------------------------------
// Differentiable JPEG (quality 80) forward pass, fused single kernel.
// image [B,3,512,512] fp32 -> out same shape.
// Tile = 16x16 pixels = 4 Y blocks + 1 Cb + 1 Cr (chroma 2x2-downsampled).
// One CTA (64 threads) per tile; each thread owns a 2x2 pixel quad.
// DCT/IDCT basis is baked as immediates (FFMA-imm); no cosine table loads.
// ---------------------------------------------------------------------------

#define IMG_H 512
#define IMG_W 512

__constant__ float c_YTAB[64] = {
    16,11,10,16,24,40,51,61,  12,12,14,19,26,58,60,55,
    14,13,16,24,40,57,69,56,  14,17,22,29,51,87,80,62,
    18,22,37,56,68,109,103,77, 24,35,55,64,81,104,113,92,
    49,64,78,87,103,121,120,101, 72,92,95,98,112,100,103,99};
__constant__ float c_CTAB[64] = {
    17,18,24,47,99,99,99,99,  18,21,26,66,99,99,99,99,
    24,26,56,99,99,99,99,99,  47,66,99,99,99,99,99,99,
    99,99,99,99,99,99,99,99,  99,99,99,99,99,99,99,99,
    99,99,99,99,99,99,99,99,  99,99,99,99,99,99,99,99};

// cos(k*pi/16) constants
#define C1 0.980785280403230449f
#define C2 0.923879532511286756f
#define C3 0.831469612302545237f
#define C4 0.707106781186547524f
#define C5 0.555570233019602225f
#define C6 0.382683432365089772f
#define C7 0.195090322016128268f

__global__ void __launch_bounds__(64)
jpeg_tile_kernel(const float* __restrict__ img, float* __restrict__ out) {
    // CT[x][u] = cos((2x+1)*u*pi/16) — constant-folded to FFMA immediates.
    constexpr float CT[8][8] = {
        {1.f,  C1,  C2,  C3,  C4,  C5,  C6,  C7},
        {1.f,  C3,  C6, -C7, -C4, -C1, -C2, -C5},
        {1.f,  C5, -C6, -C1, -C4,  C7,  C2,  C3},
        {1.f,  C7, -C2, -C5,  C4,  C3, -C6, -C1},
        {1.f, -C7, -C2,  C5,  C4, -C3, -C6,  C1},
        {1.f, -C5, -C6,  C1, -C4, -C7,  C2, -C3},
        {1.f, -C3,  C6,  C7, -C4,  C1, -C2,  C5},
        {1.f, -C1,  C2, -C3,  C4, -C5,  C6, -C7}};

    __shared__ float sAq[2][64];    // (ALPHA*0.25)/q
    __shared__ float sBq[2][64];    // (ALPHA*0.25)*q
    __shared__ float s1[6][8][9];   // blocks 0..3 = Y, 4 = Cb, 5 = Cr
    __shared__ float s2[6][8][9];

    const int t = threadIdx.x;

    // Build quant-scale tables (t indexes [u][v] flattened)
    {
        int u = t >> 3, v = t & 7;
        float au = (u == 0) ? 0.70710678118654752f : 1.f;
        float av = (v == 0) ? 0.70710678118654752f : 1.f;
        float S = au * av * 0.25f;
        float qy = c_YTAB[t] * 0.4f;   // QUALITY=80 -> FACTOR=0.4
        float qc = c_CTAB[t] * 0.4f;
        sAq[0][t] = S / qy;  sBq[0][t] = S * qy;
        sAq[1][t] = S / qc;  sBq[1][t] = S * qc;
    }

    const int tile = blockIdx.x;
    const int tx   = tile & 31;
    const int ty   = (tile >> 5) & 31;
    const int bimg = tile >> 10;

    const int qx = t & 7, qy = t >> 3;        // quad coords in tile (8x8 quads)
    const int px = tx * 16 + qx * 2;          // top-left pixel of quad
    const int py = ty * 16 + qy * 2;

    const size_t plane = (size_t)IMG_H * IMG_W;
    const float* pR = img + (size_t)bimg * 3 * plane + (size_t)py * IMG_W + px;
    const float* pG = pR + plane;
    const float* pB = pR + 2 * plane;

    float2 r0 = *(const float2*)pR;
    float2 r1 = *(const float2*)(pR + IMG_W);
    float2 g0 = *(const float2*)pG;
    float2 g1 = *(const float2*)(pG + IMG_W);
    float2 b0 = *(const float2*)pB;
    float2 b1 = *(const float2*)(pB + IMG_W);

    float Rq[2][2] = {{r0.x, r0.y}, {r1.x, r1.y}};
    float Gq[2][2] = {{g0.x, g0.y}, {g1.x, g1.y}};
    float Bq[2][2] = {{b0.x, b0.y}, {b1.x, b1.y}};

    float cbs = 0.f, crs = 0.f;
    #pragma unroll
    for (int dr = 0; dr < 2; dr++) {
        #pragma unroll
        for (int dc = 0; dc < 2; dc++) {
            float r = Rq[dr][dc] * 255.f;
            float g = Gq[dr][dc] * 255.f;
            float b = Bq[dr][dc] * 255.f;
            // Y shifted by -128 (folded DCT level shift)
            float y = 0.299f * r + 0.587f * g + 0.114f * b - 128.f;
            // Cb/Cr: +128 shift and DCT -128 cancel -> raw matrix part
            cbs += -0.168736f * r - 0.331264f * g + 0.5f      * b;
            crs +=  0.5f      * r - 0.418688f * g - 0.081312f * b;
            int prow = qy * 2 + dr, pcol = qx * 2 + dc;
            int blk = ((prow >> 3) << 1) + (pcol >> 3);
            s1[blk][prow & 7][pcol & 7] = y;
        }
    }
    s1[4][qy][qx] = cbs * 0.25f;
    s1[5][qy][qx] = crs * 0.25f;
    __syncthreads();

    // ---- Stage A: 1-D DCT along x: s2[b][u][j] = sum_x CT[x][u]*s1[b][x][j]
    if (t < 48) {
        int blk = t >> 3, j = t & 7;
        float in[8];
        #pragma unroll
        for (int x = 0; x < 8; x++) in[x] = s1[blk][x][j];
        #pragma unroll
        for (int u = 0; u < 8; u++) {
            float acc = 0.f;
            #pragma unroll
            for (int x = 0; x < 8; x++) acc += in[x] * CT[x][u];
            s2[blk][u][j] = acc;
        }
    }
    __syncthreads();

    // ---- Stage B: DCT along y, quantize w/ diff_round, start IDCT (v-sum)
    if (t < 48) {
        int blk = t >> 3, u = t & 7;
        int ti = (blk < 4) ? 0 : 1;
        float row[8];
        #pragma unroll
        for (int y = 0; y < 8; y++) row[y] = s2[blk][u][y];
        float h[8];
        #pragma unroll
        for (int v = 0; v < 8; v++) {
            float raw = 0.f;
            #pragma unroll
            for (int y = 0; y < 8; y++) raw += row[y] * CT[y][v];
            float c = raw * sAq[ti][u * 8 + v];   // coef / q
            float r = rintf(c);                   // round-half-even == jnp.round
            float d = c - r;
            h[v] = (r + d * d * d) * sBq[ti][u * 8 + v];  // * q * (ALPHA*0.25)
        }
        #pragma unroll
        for (int y = 0; y < 8; y++) {
            float acc = 0.f;
            #pragma unroll
            for (int v = 0; v < 8; v++) acc += h[v] * CT[y][v];
            s1[blk][u][y] = acc;
        }
    }
    __syncthreads();

    // ---- Stage C: finish IDCT (u-sum): s2[b][x][j] = sum_u CT[x][u]*s1[b][u][j]
    if (t < 48) {
        int blk = t >> 3, j = t & 7;
        float in[8];
        #pragma unroll
        for (int u = 0; u < 8; u++) in[u] = s1[blk][u][j];
        float add = (blk < 4) ? 128.f : 0.f;   // chroma +128/-128 cancels
        #pragma unroll
        for (int x = 0; x < 8; x++) {
            float acc = 0.f;
            #pragma unroll
            for (int u = 0; u < 8; u++) acc += in[u] * CT[x][u];
            s2[blk][x][j] = acc + add;
        }
    }
    __syncthreads();

    // ---- Writeback: upsample chroma (same value across quad), YCbCr->RGB, clip
    float cb = s2[4][qy][qx];
    float cr = s2[5][qy][qx];

    float* qR = out + (size_t)bimg * 3 * plane + (size_t)py * IMG_W + px;
    float* qG = qR + plane;
    float* qB = qR + 2 * plane;

    #pragma unroll
    for (int dr = 0; dr < 2; dr++) {
        float2 ro, go, bo;
        #pragma unroll
        for (int dc = 0; dc < 2; dc++) {
            int prow = qy * 2 + dr, pcol = qx * 2 + dc;
            int blk = ((prow >> 3) << 1) + (pcol >> 3);
            float y = s2[blk][prow & 7][pcol & 7];
            float Rv = y + 1.402f * cr;
            float Gv = y - 0.344136f * cb - 0.714136f * cr;
            float Bv = y + 1.772f * cb;
            Rv = fminf(fmaxf(Rv, 0.f), 255.f) * (1.f / 255.f);
            Gv = fminf(fmaxf(Gv, 0.f), 255.f) * (1.f / 255.f);
            Bv = fminf(fmaxf(Bv, 0.f), 255.f) * (1.f / 255.f);
            if (dc == 0) { ro.x = Rv; go.x = Gv; bo.x = Bv; }
            else         { ro.y = Rv; go.y = Gv; bo.y = Bv; }
        }
        *(float2*)(qR + dr * IMG_W) = ro;
        *(float2*)(qG + dr * IMG_W) = go;
        *(float2*)(qB + dr * IMG_W) = bo;
    }
}

extern "C" void kernel_launch(void* const* d_in, const int* in_sizes, int n_in,
                              void* d_out, int out_size) {
    const float* img = (const float*)d_in[0];
    float* out = (float*)d_out;
    int batch = in_sizes[0] / (3 * IMG_H * IMG_W);   // 32
    int tiles = batch * (IMG_H / 16) * (IMG_W / 16); // 32768

    jpeg_tile_kernel<<<tiles, 64>>>(img, out);
}